// round 1
// baseline (speedup 1.0000x reference)
#include <cuda_runtime.h>
#include <cstdint>

// Problem constants (fixed by the dataset instance)
#define BATCH 4
#define SEQ   8192
#define DMODEL 1024
#define SEG   512
#define DIL   4
#define NPROB 64   // BATCH * DIL * (SEQ/DIL/SEG) = 4*4*4

// 64 MB scratch for scores / attention probabilities: [NPROB][SEG][SEG]
__device__ float g_S[(size_t)NPROB * SEG * SEG];

// ---------------------------------------------------------------------------
// tf32 helpers
// ---------------------------------------------------------------------------
__device__ __forceinline__ uint32_t f32_to_tf32(float x) {
    uint32_t r;
    asm("cvt.rna.tf32.f32 %0, %1;" : "=r"(r) : "f"(x));
    return r;
}

__device__ __forceinline__ void split_tf32(float v, uint32_t& hi, uint32_t& lo) {
    hi = f32_to_tf32(v);
    lo = f32_to_tf32(v - __uint_as_float(hi));
}

__device__ __forceinline__ void mma_tf32(float c[4],
                                         uint32_t a0, uint32_t a1, uint32_t a2, uint32_t a3,
                                         uint32_t b0, uint32_t b1) {
    asm volatile(
        "mma.sync.aligned.m16n8k8.row.col.f32.tf32.tf32.f32 "
        "{%0,%1,%2,%3}, {%4,%5,%6,%7}, {%8,%9}, {%0,%1,%2,%3};"
        : "+f"(c[0]), "+f"(c[1]), "+f"(c[2]), "+f"(c[3])
        : "r"(a0), "r"(a1), "r"(a2), "r"(a3), "r"(b0), "r"(b1));
}

// Decode problem id -> base pointer of its dilated row block.
// Problem p: b = p>>4, off = (p>>2)&3, seg = p&3.
// Local row t (0..511) lives at global seq index off + 4*(seg*512 + t).
__device__ __forceinline__ const float* prob_base(const float* x, int p) {
    int b = p >> 4, off = (p >> 2) & 3, seg = p & 3;
    return x + ((size_t)b * SEQ + off + (size_t)4 * seg * SEG) * DMODEL;
}

// ---------------------------------------------------------------------------
// Kernel 1: S[p,i,j] = (1/32) * sum_k X[i,k] X[j,k]   (3xTF32 split)
// Grid: (16 tiles, 64 problems), 256 threads (8 warps, warp tile 64x32)
// ---------------------------------------------------------------------------
__global__ __launch_bounds__(256) void qk_kernel(const float* __restrict__ x) {
    const int p = blockIdx.y;
    const float* xb = prob_base(x, p);
    const int ti = blockIdx.x >> 2;   // row tile 0..3
    const int tj = blockIdx.x & 3;    // col tile 0..3

    // stride 20 floats: bank(r,c) = (4r + c) mod 32 -> conflict-free fragment loads
    __shared__ float sA_hi[128][20], sA_lo[128][20];
    __shared__ float sB_hi[128][20], sB_lo[128][20];

    const int tid = threadIdx.x;
    const int wid = tid >> 5, lane = tid & 31;
    const int wm = wid & 1, wn = wid >> 1;      // warp grid 2 (rows) x 4 (cols)
    const int g = lane >> 2, tg = lane & 3;

    float c[4][4][4];
#pragma unroll
    for (int m = 0; m < 4; m++)
#pragma unroll
        for (int n = 0; n < 4; n++)
#pragma unroll
            for (int q = 0; q < 4; q++) c[m][n][q] = 0.f;

    const int lr = tid >> 2;        // 0..63 (row within half-tile)
    const int lc = (tid & 3) * 4;   // k-col * 4

    for (int kc = 0; kc < DMODEL / 16; kc++) {
        const int k0 = kc * 16;
        __syncthreads();
#pragma unroll
        for (int pass = 0; pass < 2; pass++) {
            const int r = lr + pass * 64;
            float4 va = *(const float4*)(xb + (size_t)(ti * 128 + r) * 4 * DMODEL + k0 + lc);
            float4 vb = *(const float4*)(xb + (size_t)(tj * 128 + r) * 4 * DMODEL + k0 + lc);
            uint4 h, l;
            split_tf32(va.x, h.x, l.x); split_tf32(va.y, h.y, l.y);
            split_tf32(va.z, h.z, l.z); split_tf32(va.w, h.w, l.w);
            *(uint4*)&sA_hi[r][lc] = h;
            *(uint4*)&sA_lo[r][lc] = l;
            split_tf32(vb.x, h.x, l.x); split_tf32(vb.y, h.y, l.y);
            split_tf32(vb.z, h.z, l.z); split_tf32(vb.w, h.w, l.w);
            *(uint4*)&sB_hi[r][lc] = h;
            *(uint4*)&sB_lo[r][lc] = l;
        }
        __syncthreads();

#pragma unroll
        for (int ks = 0; ks < 2; ks++) {
            const int kb = ks * 8;
            uint32_t bh[4][2], bl[4][2];
#pragma unroll
            for (int n = 0; n < 4; n++) {
                const int col = wn * 32 + n * 8 + g;
                bh[n][0] = *(const uint32_t*)&sB_hi[col][kb + tg];
                bh[n][1] = *(const uint32_t*)&sB_hi[col][kb + tg + 4];
                bl[n][0] = *(const uint32_t*)&sB_lo[col][kb + tg];
                bl[n][1] = *(const uint32_t*)&sB_lo[col][kb + tg + 4];
            }
#pragma unroll
            for (int m = 0; m < 4; m++) {
                const int row = wm * 64 + m * 16;
                uint32_t ah0 = *(const uint32_t*)&sA_hi[row + g][kb + tg];
                uint32_t ah1 = *(const uint32_t*)&sA_hi[row + g + 8][kb + tg];
                uint32_t ah2 = *(const uint32_t*)&sA_hi[row + g][kb + tg + 4];
                uint32_t ah3 = *(const uint32_t*)&sA_hi[row + g + 8][kb + tg + 4];
                uint32_t al0 = *(const uint32_t*)&sA_lo[row + g][kb + tg];
                uint32_t al1 = *(const uint32_t*)&sA_lo[row + g + 8][kb + tg];
                uint32_t al2 = *(const uint32_t*)&sA_lo[row + g][kb + tg + 4];
                uint32_t al3 = *(const uint32_t*)&sA_lo[row + g + 8][kb + tg + 4];
#pragma unroll
                for (int n = 0; n < 4; n++) {
                    mma_tf32(c[m][n], ah0, ah1, ah2, ah3, bh[n][0], bh[n][1]);
                    mma_tf32(c[m][n], ah0, ah1, ah2, ah3, bl[n][0], bl[n][1]);
                    mma_tf32(c[m][n], al0, al1, al2, al3, bh[n][0], bh[n][1]);
                }
            }
        }
    }

    const float scale = 0.03125f;  // 1/sqrt(1024)
    float* Sp = g_S + (size_t)p * SEG * SEG;
#pragma unroll
    for (int m = 0; m < 4; m++) {
#pragma unroll
        for (int n = 0; n < 4; n++) {
            const int row0 = ti * 128 + wm * 64 + m * 16 + g;
            const int col = tj * 128 + wn * 32 + n * 8 + 2 * tg;
            *(float2*)&Sp[(size_t)row0 * SEG + col] =
                make_float2(c[m][n][0] * scale, c[m][n][1] * scale);
            *(float2*)&Sp[(size_t)(row0 + 8) * SEG + col] =
                make_float2(c[m][n][2] * scale, c[m][n][3] * scale);
        }
    }
}

// ---------------------------------------------------------------------------
// Kernel 2: row softmax in place on g_S. One block (256 thr) per row of 512.
// ---------------------------------------------------------------------------
__global__ __launch_bounds__(256) void softmax_kernel() {
    __shared__ float sm[8];
    float* row = g_S + (size_t)blockIdx.x * SEG;
    const int tid = threadIdx.x;

    float v0 = row[tid];
    float v1 = row[tid + 256];

    float m = fmaxf(v0, v1);
#pragma unroll
    for (int o = 16; o; o >>= 1) m = fmaxf(m, __shfl_xor_sync(0xffffffffu, m, o));
    if ((tid & 31) == 0) sm[tid >> 5] = m;
    __syncthreads();
    float M = sm[0];
#pragma unroll
    for (int i = 1; i < 8; i++) M = fmaxf(M, sm[i]);
    __syncthreads();

    float e0 = __expf(v0 - M), e1 = __expf(v1 - M);
    float s = e0 + e1;
#pragma unroll
    for (int o = 16; o; o >>= 1) s += __shfl_xor_sync(0xffffffffu, s, o);
    if ((tid & 31) == 0) sm[tid >> 5] = s;
    __syncthreads();
    float T = 0.f;
#pragma unroll
    for (int i = 0; i < 8; i++) T += sm[i];
    const float inv = 1.0f / T;

    row[tid] = e0 * inv;
    row[tid + 256] = e1 * inv;
}

// ---------------------------------------------------------------------------
// Kernel 3: out[rows of p] = 0.25 * P(512x512) @ X(512x1024), 3xTF32 split.
// Grid: (32 tiles: 4 m x 8 n, 64 problems), 256 threads.
// ---------------------------------------------------------------------------
__global__ __launch_bounds__(256) void pv_kernel(const float* __restrict__ x,
                                                 float* __restrict__ out) {
    const int p = blockIdx.y;
    const float* xb = prob_base(x, p);
    float* ob = out + (xb - x);  // same layout as x
    const int tm = blockIdx.x >> 3;  // 0..3 (output row tiles)
    const int tn = blockIdx.x & 7;   // 0..7 (d-column tiles)

    __shared__ float sP_hi[128][20], sP_lo[128][20];
    // [k][136]: 136 mod 32 = 8 -> conflict-free B fragment loads
    __shared__ float sV_hi[16][136], sV_lo[16][136];

    const float* Pp = g_S + (size_t)p * SEG * SEG;

    const int tid = threadIdx.x;
    const int wid = tid >> 5, lane = tid & 31;
    const int wm = wid & 1, wn = wid >> 1;
    const int g = lane >> 2, tg = lane & 3;

    float c[4][4][4];
#pragma unroll
    for (int m = 0; m < 4; m++)
#pragma unroll
        for (int n = 0; n < 4; n++)
#pragma unroll
            for (int q = 0; q < 4; q++) c[m][n][q] = 0.f;

    const int lr = tid >> 2;
    const int lc = (tid & 3) * 4;

    for (int kc = 0; kc < SEG / 16; kc++) {
        const int k0 = kc * 16;
        __syncthreads();
        // stage P tile (rows = output rows, cols = k)
#pragma unroll
        for (int pass = 0; pass < 2; pass++) {
            const int r = lr + pass * 64;
            float4 v = *(const float4*)&Pp[(size_t)(tm * 128 + r) * SEG + k0 + lc];
            uint4 h, l;
            split_tf32(v.x, h.x, l.x); split_tf32(v.y, h.y, l.y);
            split_tf32(v.z, h.z, l.z); split_tf32(v.w, h.w, l.w);
            *(uint4*)&sP_hi[r][lc] = h;
            *(uint4*)&sP_lo[r][lc] = l;
        }
        // stage V tile [k=16][n=128], fully coalesced rows
#pragma unroll
        for (int pass = 0; pass < 2; pass++) {
            const int idx = tid + pass * 256;
            const int k = idx >> 5;          // 0..15
            const int c4 = (idx & 31) * 4;   // 0..124
            float4 v = *(const float4*)(xb + (size_t)(k0 + k) * 4 * DMODEL + tn * 128 + c4);
            uint4 h, l;
            split_tf32(v.x, h.x, l.x); split_tf32(v.y, h.y, l.y);
            split_tf32(v.z, h.z, l.z); split_tf32(v.w, h.w, l.w);
            *(uint4*)&sV_hi[k][c4] = h;
            *(uint4*)&sV_lo[k][c4] = l;
        }
        __syncthreads();

#pragma unroll
        for (int ks = 0; ks < 2; ks++) {
            const int kb = ks * 8;
            uint32_t bh[4][2], bl[4][2];
#pragma unroll
            for (int n = 0; n < 4; n++) {
                const int col = wn * 32 + n * 8 + g;
                bh[n][0] = *(const uint32_t*)&sV_hi[kb + tg][col];
                bh[n][1] = *(const uint32_t*)&sV_hi[kb + tg + 4][col];
                bl[n][0] = *(const uint32_t*)&sV_lo[kb + tg][col];
                bl[n][1] = *(const uint32_t*)&sV_lo[kb + tg + 4][col];
            }
#pragma unroll
            for (int m = 0; m < 4; m++) {
                const int row = wm * 64 + m * 16;
                uint32_t ah0 = *(const uint32_t*)&sP_hi[row + g][kb + tg];
                uint32_t ah1 = *(const uint32_t*)&sP_hi[row + g + 8][kb + tg];
                uint32_t ah2 = *(const uint32_t*)&sP_hi[row + g][kb + tg + 4];
                uint32_t ah3 = *(const uint32_t*)&sP_hi[row + g + 8][kb + tg + 4];
                uint32_t al0 = *(const uint32_t*)&sP_lo[row + g][kb + tg];
                uint32_t al1 = *(const uint32_t*)&sP_lo[row + g + 8][kb + tg];
                uint32_t al2 = *(const uint32_t*)&sP_lo[row + g][kb + tg + 4];
                uint32_t al3 = *(const uint32_t*)&sP_lo[row + g + 8][kb + tg + 4];
#pragma unroll
                for (int n = 0; n < 4; n++) {
                    mma_tf32(c[m][n], ah0, ah1, ah2, ah3, bh[n][0], bh[n][1]);
                    mma_tf32(c[m][n], ah0, ah1, ah2, ah3, bl[n][0], bl[n][1]);
                    mma_tf32(c[m][n], al0, al1, al2, al3, bh[n][0], bh[n][1]);
                }
            }
        }
    }

    const float w = 0.25f;  // softmax(uniform 1/4) weights
#pragma unroll
    for (int m = 0; m < 4; m++) {
#pragma unroll
        for (int n = 0; n < 4; n++) {
            const int row0 = tm * 128 + wm * 64 + m * 16 + g;
            const int col = tn * 128 + wn * 32 + n * 8 + 2 * tg;
            *(float2*)(ob + (size_t)row0 * 4 * DMODEL + col) =
                make_float2(c[m][n][0] * w, c[m][n][1] * w);
            *(float2*)(ob + (size_t)(row0 + 8) * 4 * DMODEL + col) =
                make_float2(c[m][n][2] * w, c[m][n][3] * w);
        }
    }
}

// ---------------------------------------------------------------------------
extern "C" void kernel_launch(void* const* d_in, const int* in_sizes, int n_in,
                              void* d_out, int out_size) {
    const float* x = (const float*)d_in[0];
    float* out = (float*)d_out;
    (void)in_sizes; (void)n_in; (void)out_size;

    qk_kernel<<<dim3(16, NPROB), 256>>>(x);
    softmax_kernel<<<NPROB * SEG, 256>>>();
    pv_kernel<<<dim3(32, NPROB), 256>>>(x, out);
}

// round 8
// speedup vs baseline: 1.4041x; 1.4041x over previous
#include <cuda_runtime.h>
#include <cuda_bf16.h>
#include <cstdint>

#define NPROB 64
#define SEG   512
#define DM    1024
#define BK    32      // k-chunk per smem stage
#define PADR  40      // smem row stride in bf16 (20 banks -> conflict-free frags)

// ---------------------------------------------------------------------------
// Device scratch (no allocations allowed)
// ---------------------------------------------------------------------------
__device__ float         g_S  [(size_t)NPROB * SEG * SEG];   // fp32 scores
__device__ __nv_bfloat16 g_Xh [(size_t)NPROB * SEG * DM];    // X hi, K-major
__device__ __nv_bfloat16 g_Xl [(size_t)NPROB * SEG * DM];    // X lo, K-major
__device__ __nv_bfloat16 g_XTh[(size_t)NPROB * DM * SEG];    // X hi, [d][s]
__device__ __nv_bfloat16 g_XTl[(size_t)NPROB * DM * SEG];    // X lo, [d][s]
__device__ __nv_bfloat16 g_Ph [(size_t)NPROB * SEG * SEG];   // P hi
__device__ __nv_bfloat16 g_Pl [(size_t)NPROB * SEG * SEG];   // P lo

// ---------------------------------------------------------------------------
// bf16 m16n8k16 mma (legacy pipe, plain PTX -> valid on compute_103)
// ---------------------------------------------------------------------------
__device__ __forceinline__ void mma_bf16(float c[4],
                                         uint32_t a0, uint32_t a1, uint32_t a2, uint32_t a3,
                                         uint32_t b0, uint32_t b1) {
    asm volatile(
        "mma.sync.aligned.m16n8k16.row.col.f32.bf16.bf16.f32 "
        "{%0,%1,%2,%3}, {%4,%5,%6,%7}, {%8,%9}, {%0,%1,%2,%3};"
        : "+f"(c[0]), "+f"(c[1]), "+f"(c[2]), "+f"(c[3])
        : "r"(a0), "r"(a1), "r"(a2), "r"(a3), "r"(b0), "r"(b1));
}

// ---------------------------------------------------------------------------
// Kernel 0: de-stride + split fp32 -> bf16 hi/lo, K-major and transposed.
// grid (64, 64), 256 threads. Tile = 64 seq rows x 128 d cols.
// ---------------------------------------------------------------------------
__global__ __launch_bounds__(256) void preconvert_kernel(const float* __restrict__ x) {
    __shared__ uint32_t sT[128 * 65];  // [d][s]: hi<<16 | lo

    const int p = blockIdx.y;
    const int b = p >> 4, off = (p >> 2) & 3, sg = p & 3;
    const int ts = blockIdx.x >> 3;   // seq tile 0..7
    const int td = blockIdx.x & 7;    // d tile 0..7
    const int tid = threadIdx.x;

    __nv_bfloat16* Xh = g_Xh + (size_t)p * SEG * DM;
    __nv_bfloat16* Xl = g_Xl + (size_t)p * SEG * DM;

#pragma unroll 4
    for (int i = 0; i < 32; i++) {
        const int idx = tid + 256 * i;
        const int row = idx >> 7;          // 0..63
        const int d = idx & 127;
        const int s = ts * 64 + row;
        const int D = td * 128 + d;
        const size_t srow = (size_t)b * 8192 + off + 4 * ((size_t)sg * 512 + s);
        const float v = x[srow * DM + D];
        const __nv_bfloat16 h = __float2bfloat16_rn(v);
        const __nv_bfloat16 l = __float2bfloat16_rn(v - __bfloat162float(h));
        Xh[(size_t)s * DM + D] = h;
        Xl[(size_t)s * DM + D] = l;
        sT[d * 65 + row] = ((uint32_t)__bfloat16_as_ushort(h) << 16) |
                           (uint32_t)__bfloat16_as_ushort(l);
    }
    __syncthreads();

    __nv_bfloat16* XTh = g_XTh + (size_t)p * DM * SEG;
    __nv_bfloat16* XTl = g_XTl + (size_t)p * DM * SEG;
#pragma unroll
    for (int i = 0; i < 8; i++) {
        const int idx = tid + 256 * i;     // 0..2047
        const int d = idx >> 4;            // 0..127
        const int sq = idx & 15;           // 4 s-values each
        uint32_t v0 = sT[d * 65 + 4 * sq + 0];
        uint32_t v1 = sT[d * 65 + 4 * sq + 1];
        uint32_t v2 = sT[d * 65 + 4 * sq + 2];
        uint32_t v3 = sT[d * 65 + 4 * sq + 3];
        uint2 H, L;
        H.x = (v0 >> 16) | (v1 & 0xFFFF0000u);
        H.y = (v2 >> 16) | (v3 & 0xFFFF0000u);
        L.x = (v0 & 0xFFFFu) | (v1 << 16);
        L.y = (v2 & 0xFFFFu) | (v3 << 16);
        const size_t o = (size_t)(td * 128 + d) * SEG + ts * 64 + 4 * sq;
        *(uint2*)(XTh + o) = H;
        *(uint2*)(XTl + o) = L;
    }
}

// ---------------------------------------------------------------------------
// Stage a [128 x BK] bf16 tile into padded smem. 512 uint4 / 256 threads.
// ---------------------------------------------------------------------------
__device__ __forceinline__ void stage_tile(__nv_bfloat16 (*dst)[PADR],
                                           const __nv_bfloat16* __restrict__ src,
                                           int ld, int k0, int tid) {
#pragma unroll
    for (int j = tid; j < 512; j += 256) {
        const int row = j >> 2, q = j & 3;
        uint4 v = *(const uint4*)(src + (size_t)row * ld + k0 + q * 8);
        *(uint4*)&dst[row][q * 8] = v;
    }
}

// ---------------------------------------------------------------------------
// Core bf16 split-GEMM compute for one k-chunk already staged in smem.
// Warp tile 64x32 (2x4 warp grid). 3 products: hh, hl, lh.
// ---------------------------------------------------------------------------
__device__ __forceinline__ void compute_chunk(float c[4][4][4],
                                              const __nv_bfloat16 (*sAh)[PADR],
                                              const __nv_bfloat16 (*sAl)[PADR],
                                              const __nv_bfloat16 (*sBh)[PADR],
                                              const __nv_bfloat16 (*sBl)[PADR],
                                              int wm, int wn, int g, int tg) {
#pragma unroll
    for (int ks = 0; ks < 2; ks++) {
        const int kb = ks * 16;
        uint32_t bh[4][2], bl[4][2];
#pragma unroll
        for (int n = 0; n < 4; n++) {
            const int col = wn * 32 + n * 8 + g;
            bh[n][0] = *(const uint32_t*)&sBh[col][kb + 2 * tg];
            bh[n][1] = *(const uint32_t*)&sBh[col][kb + 2 * tg + 8];
            bl[n][0] = *(const uint32_t*)&sBl[col][kb + 2 * tg];
            bl[n][1] = *(const uint32_t*)&sBl[col][kb + 2 * tg + 8];
        }
#pragma unroll
        for (int m = 0; m < 4; m++) {
            const int row = wm * 64 + m * 16;
            uint32_t ah0 = *(const uint32_t*)&sAh[row + g][kb + 2 * tg];
            uint32_t ah1 = *(const uint32_t*)&sAh[row + g + 8][kb + 2 * tg];
            uint32_t ah2 = *(const uint32_t*)&sAh[row + g][kb + 2 * tg + 8];
            uint32_t ah3 = *(const uint32_t*)&sAh[row + g + 8][kb + 2 * tg + 8];
            uint32_t al0 = *(const uint32_t*)&sAl[row + g][kb + 2 * tg];
            uint32_t al1 = *(const uint32_t*)&sAl[row + g + 8][kb + 2 * tg];
            uint32_t al2 = *(const uint32_t*)&sAl[row + g][kb + 2 * tg + 8];
            uint32_t al3 = *(const uint32_t*)&sAl[row + g + 8][kb + 2 * tg + 8];
#pragma unroll
            for (int n = 0; n < 4; n++) {
                mma_bf16(c[m][n], ah0, ah1, ah2, ah3, bh[n][0], bh[n][1]);
                mma_bf16(c[m][n], ah0, ah1, ah2, ah3, bl[n][0], bl[n][1]);
                mma_bf16(c[m][n], al0, al1, al2, al3, bh[n][0], bh[n][1]);
            }
        }
    }
}

// ---------------------------------------------------------------------------
// Kernel 1: S = (1/32) X X^T. CTA tile 128x128, grid (16, 64).
// ---------------------------------------------------------------------------
__global__ __launch_bounds__(256) void qk_kernel() {
    __shared__ __nv_bfloat16 sAh[128][PADR], sAl[128][PADR];
    __shared__ __nv_bfloat16 sBh[128][PADR], sBl[128][PADR];

    const int p = blockIdx.y;
    const int ti = blockIdx.x >> 2, tj = blockIdx.x & 3;
    const int tid = threadIdx.x;
    const int wid = tid >> 5, lane = tid & 31;
    const int wm = wid & 1, wn = wid >> 1;
    const int g = lane >> 2, tg = lane & 3;

    const __nv_bfloat16* Ah = g_Xh + (size_t)p * SEG * DM + (size_t)ti * 128 * DM;
    const __nv_bfloat16* Al = g_Xl + (size_t)p * SEG * DM + (size_t)ti * 128 * DM;
    const __nv_bfloat16* Bh = g_Xh + (size_t)p * SEG * DM + (size_t)tj * 128 * DM;
    const __nv_bfloat16* Bl = g_Xl + (size_t)p * SEG * DM + (size_t)tj * 128 * DM;

    float c[4][4][4];
#pragma unroll
    for (int m = 0; m < 4; m++)
#pragma unroll
        for (int n = 0; n < 4; n++)
#pragma unroll
            for (int q = 0; q < 4; q++) c[m][n][q] = 0.f;

    for (int kc = 0; kc < DM / BK; kc++) {
        const int k0 = kc * BK;
        __syncthreads();
        stage_tile(sAh, Ah, DM, k0, tid);
        stage_tile(sAl, Al, DM, k0, tid);
        stage_tile(sBh, Bh, DM, k0, tid);
        stage_tile(sBl, Bl, DM, k0, tid);
        __syncthreads();
        compute_chunk(c, sAh, sAl, sBh, sBl, wm, wn, g, tg);
    }

    const float scale = 0.03125f;  // 1/sqrt(1024)
    float* Sp = g_S + (size_t)p * SEG * SEG;
#pragma unroll
    for (int m = 0; m < 4; m++) {
#pragma unroll
        for (int n = 0; n < 4; n++) {
            const int row0 = ti * 128 + wm * 64 + m * 16 + g;
            const int col = tj * 128 + wn * 32 + n * 8 + 2 * tg;
            *(float2*)&Sp[(size_t)row0 * SEG + col] =
                make_float2(c[m][n][0] * scale, c[m][n][1] * scale);
            *(float2*)&Sp[(size_t)(row0 + 8) * SEG + col] =
                make_float2(c[m][n][2] * scale, c[m][n][3] * scale);
        }
    }
}

// ---------------------------------------------------------------------------
// Kernel 2: row softmax on g_S -> P hi/lo bf16. 1 block (256 thr) per row.
// ---------------------------------------------------------------------------
__global__ __launch_bounds__(256) void softmax_kernel() {
    __shared__ float smx[8];
    const size_t r = blockIdx.x;
    const float* row = g_S + r * SEG;
    const int tid = threadIdx.x;

    float v0 = row[tid], v1 = row[tid + 256];
    float m = fmaxf(v0, v1);
#pragma unroll
    for (int o = 16; o; o >>= 1) m = fmaxf(m, __shfl_xor_sync(~0u, m, o));
    if ((tid & 31) == 0) smx[tid >> 5] = m;
    __syncthreads();
    float M = smx[0];
#pragma unroll
    for (int i = 1; i < 8; i++) M = fmaxf(M, smx[i]);
    __syncthreads();

    float e0 = __expf(v0 - M), e1 = __expf(v1 - M);
    float s = e0 + e1;
#pragma unroll
    for (int o = 16; o; o >>= 1) s += __shfl_xor_sync(~0u, s, o);
    if ((tid & 31) == 0) smx[tid >> 5] = s;
    __syncthreads();
    float T = 0.f;
#pragma unroll
    for (int i = 0; i < 8; i++) T += smx[i];
    const float inv = 1.0f / T;

    const float p0 = e0 * inv, p1 = e1 * inv;
    __nv_bfloat16 h0 = __float2bfloat16_rn(p0);
    __nv_bfloat16 l0 = __float2bfloat16_rn(p0 - __bfloat162float(h0));
    __nv_bfloat16 h1 = __float2bfloat16_rn(p1);
    __nv_bfloat16 l1 = __float2bfloat16_rn(p1 - __bfloat162float(h1));
    g_Ph[r * SEG + tid] = h0;        g_Pl[r * SEG + tid] = l0;
    g_Ph[r * SEG + tid + 256] = h1;  g_Pl[r * SEG + tid + 256] = l1;
}

// ---------------------------------------------------------------------------
// Kernel 3: O = 0.25 * P @ X. CTA tile 128(m,seq) x 128(n,d), grid (32, 64).
// B operand staged from transposed X: row = d, k = s (contiguous).
// ---------------------------------------------------------------------------
__global__ __launch_bounds__(256) void pv_kernel(float* __restrict__ out) {
    __shared__ __nv_bfloat16 sAh[128][PADR], sAl[128][PADR];
    __shared__ __nv_bfloat16 sBh[128][PADR], sBl[128][PADR];

    const int p = blockIdx.y;
    const int tm = blockIdx.x >> 3;   // 0..3 (seq row tiles)
    const int tn = blockIdx.x & 7;    // 0..7 (d col tiles)
    const int tid = threadIdx.x;
    const int wid = tid >> 5, lane = tid & 31;
    const int wm = wid & 1, wn = wid >> 1;
    const int g = lane >> 2, tg = lane & 3;

    const __nv_bfloat16* Ah = g_Ph + (size_t)p * SEG * SEG + (size_t)tm * 128 * SEG;
    const __nv_bfloat16* Al = g_Pl + (size_t)p * SEG * SEG + (size_t)tm * 128 * SEG;
    const __nv_bfloat16* Bh = g_XTh + (size_t)p * DM * SEG + (size_t)tn * 128 * SEG;
    const __nv_bfloat16* Bl = g_XTl + (size_t)p * DM * SEG + (size_t)tn * 128 * SEG;

    float c[4][4][4];
#pragma unroll
    for (int m = 0; m < 4; m++)
#pragma unroll
        for (int n = 0; n < 4; n++)
#pragma unroll
            for (int q = 0; q < 4; q++) c[m][n][q] = 0.f;

    for (int kc = 0; kc < SEG / BK; kc++) {
        const int k0 = kc * BK;
        __syncthreads();
        stage_tile(sAh, Ah, SEG, k0, tid);
        stage_tile(sAl, Al, SEG, k0, tid);
        stage_tile(sBh, Bh, SEG, k0, tid);
        stage_tile(sBl, Bl, SEG, k0, tid);
        __syncthreads();
        compute_chunk(c, sAh, sAl, sBh, sBl, wm, wn, g, tg);
    }

    const int b = p >> 4, off = (p >> 2) & 3, sg = p & 3;
    const float wt = 0.25f;
#pragma unroll
    for (int m = 0; m < 4; m++) {
#pragma unroll
        for (int n = 0; n < 4; n++) {
            const int row0 = tm * 128 + wm * 64 + m * 16 + g;
            const int col = tn * 128 + wn * 32 + n * 8 + 2 * tg;
            const size_t or0 = ((size_t)b * 8192 + off + 4 * ((size_t)sg * 512 + row0)) * DM;
            const size_t or1 = ((size_t)b * 8192 + off + 4 * ((size_t)sg * 512 + row0 + 8)) * DM;
            *(float2*)(out + or0 + col) =
                make_float2(c[m][n][0] * wt, c[m][n][1] * wt);
            *(float2*)(out + or1 + col) =
                make_float2(c[m][n][2] * wt, c[m][n][3] * wt);
        }
    }
}

// ---------------------------------------------------------------------------
extern "C" void kernel_launch(void* const* d_in, const int* in_sizes, int n_in,
                              void* d_out, int out_size) {
    const float* x = (const float*)d_in[0];
    float* out = (float*)d_out;
    (void)in_sizes; (void)n_in; (void)out_size;

    preconvert_kernel<<<dim3(64, NPROB), 256>>>(x);
    qk_kernel<<<dim3(16, NPROB), 256>>>();
    softmax_kernel<<<NPROB * SEG, 256>>>();
    pv_kernel<<<dim3(32, NPROB), 256>>>(out);
}

// round 15
// speedup vs baseline: 1.6328x; 1.1629x over previous
#include <cuda_runtime.h>
#include <cuda_bf16.h>
#include <cstdint>

#define NPROB 64
#define SEG   512
#define DM    1024
#define BK    32                      // k-chunk per stage
#define PADR  40                      // smem row stride in bf16 (conflict-free)
#define TILE_B  (128 * PADR * 2)      // 10240 bytes per tile
#define STAGE_B (4 * TILE_B)          // Ah,Al,Bh,Bl = 40960 bytes
#define SMEM_T  (2 * STAGE_B)         // double buffered = 81920 bytes

// ---------------------------------------------------------------------------
// Device scratch (no allocations allowed)
// ---------------------------------------------------------------------------
__device__ float         g_S  [(size_t)NPROB * SEG * SEG];   // fp32 scores
__device__ __nv_bfloat16 g_Xh [(size_t)NPROB * SEG * DM];    // X hi, K-major
__device__ __nv_bfloat16 g_Xl [(size_t)NPROB * SEG * DM];    // X lo, K-major
__device__ __nv_bfloat16 g_XTh[(size_t)NPROB * DM * SEG];    // X hi, [d][s]
__device__ __nv_bfloat16 g_XTl[(size_t)NPROB * DM * SEG];    // X lo, [d][s]
__device__ __nv_bfloat16 g_Ph [(size_t)NPROB * SEG * SEG];   // P hi
__device__ __nv_bfloat16 g_Pl [(size_t)NPROB * SEG * SEG];   // P lo

// ---------------------------------------------------------------------------
// PTX helpers (all plain sm_80-era features, valid at compute_103)
// ---------------------------------------------------------------------------
__device__ __forceinline__ uint32_t smem_u32(const void* p) {
    uint32_t a;
    asm("{ .reg .u64 t; cvta.to.shared.u64 t, %1; cvt.u32.u64 %0, t; }" : "=r"(a) : "l"(p));
    return a;
}

__device__ __forceinline__ void mma_bf16(float c[4],
                                         uint32_t a0, uint32_t a1, uint32_t a2, uint32_t a3,
                                         uint32_t b0, uint32_t b1) {
    asm volatile(
        "mma.sync.aligned.m16n8k16.row.col.f32.bf16.bf16.f32 "
        "{%0,%1,%2,%3}, {%4,%5,%6,%7}, {%8,%9}, {%0,%1,%2,%3};"
        : "+f"(c[0]), "+f"(c[1]), "+f"(c[2]), "+f"(c[3])
        : "r"(a0), "r"(a1), "r"(a2), "r"(a3), "r"(b0), "r"(b1));
}

__device__ __forceinline__ void ldsm4(uint32_t& r0, uint32_t& r1,
                                      uint32_t& r2, uint32_t& r3, uint32_t addr) {
    asm volatile("ldmatrix.sync.aligned.m8n8.x4.shared.b16 {%0,%1,%2,%3}, [%4];"
                 : "=r"(r0), "=r"(r1), "=r"(r2), "=r"(r3) : "r"(addr));
}

__device__ __forceinline__ void cp16(uint32_t dst, const void* src) {
    asm volatile("cp.async.cg.shared.global [%0], [%1], 16;" :: "r"(dst), "l"(src));
}
#define CP_COMMIT() asm volatile("cp.async.commit_group;" ::: "memory")
#define CP_WAIT1()  asm volatile("cp.async.wait_group 1;" ::: "memory")
#define CP_WAIT0()  asm volatile("cp.async.wait_group 0;" ::: "memory")

// ---------------------------------------------------------------------------
// Kernel 0: de-stride + split fp32 -> bf16 hi/lo, K-major and transposed.
// ---------------------------------------------------------------------------
__global__ __launch_bounds__(256) void preconvert_kernel(const float* __restrict__ x) {
    __shared__ uint32_t sT[128 * 65];  // [d][s]: hi<<16 | lo

    const int p = blockIdx.y;
    const int b = p >> 4, off = (p >> 2) & 3, sg = p & 3;
    const int ts = blockIdx.x >> 3;
    const int td = blockIdx.x & 7;
    const int tid = threadIdx.x;

    __nv_bfloat16* Xh = g_Xh + (size_t)p * SEG * DM;
    __nv_bfloat16* Xl = g_Xl + (size_t)p * SEG * DM;

#pragma unroll 4
    for (int i = 0; i < 32; i++) {
        const int idx = tid + 256 * i;
        const int row = idx >> 7;
        const int d = idx & 127;
        const int s = ts * 64 + row;
        const int D = td * 128 + d;
        const size_t srow = (size_t)b * 8192 + off + 4 * ((size_t)sg * 512 + s);
        const float v = x[srow * DM + D];
        const __nv_bfloat16 h = __float2bfloat16_rn(v);
        const __nv_bfloat16 l = __float2bfloat16_rn(v - __bfloat162float(h));
        Xh[(size_t)s * DM + D] = h;
        Xl[(size_t)s * DM + D] = l;
        sT[d * 65 + row] = ((uint32_t)__bfloat16_as_ushort(h) << 16) |
                           (uint32_t)__bfloat16_as_ushort(l);
    }
    __syncthreads();

    __nv_bfloat16* XTh = g_XTh + (size_t)p * DM * SEG;
    __nv_bfloat16* XTl = g_XTl + (size_t)p * DM * SEG;
#pragma unroll
    for (int i = 0; i < 8; i++) {
        const int idx = tid + 256 * i;
        const int d = idx >> 4;
        const int sq = idx & 15;
        uint32_t v0 = sT[d * 65 + 4 * sq + 0];
        uint32_t v1 = sT[d * 65 + 4 * sq + 1];
        uint32_t v2 = sT[d * 65 + 4 * sq + 2];
        uint32_t v3 = sT[d * 65 + 4 * sq + 3];
        uint2 H, L;
        H.x = (v0 >> 16) | (v1 & 0xFFFF0000u);
        H.y = (v2 >> 16) | (v3 & 0xFFFF0000u);
        L.x = (v0 & 0xFFFFu) | (v1 << 16);
        L.y = (v2 & 0xFFFFu) | (v3 << 16);
        const size_t o = (size_t)(td * 128 + d) * SEG + ts * 64 + 4 * sq;
        *(uint2*)(XTh + o) = H;
        *(uint2*)(XTl + o) = L;
    }
}

// ---------------------------------------------------------------------------
// Async-stage one [128 x BK] bf16 tile into padded smem (cp.async 16B).
// ---------------------------------------------------------------------------
__device__ __forceinline__ void stage_async(uint32_t dst,
                                            const __nv_bfloat16* __restrict__ src,
                                            int ld, int k0, int tid) {
#pragma unroll
    for (int j = tid; j < 512; j += 256) {
        const int row = j >> 2, q = j & 3;
        cp16(dst + (uint32_t)(row * PADR + q * 8) * 2,
             src + (size_t)row * ld + k0 + q * 8);
    }
}

__device__ __forceinline__ void stage_all(uint32_t buf,
                                          const __nv_bfloat16* Ah, const __nv_bfloat16* Al,
                                          const __nv_bfloat16* Bh, const __nv_bfloat16* Bl,
                                          int ld, int k0, int tid) {
    stage_async(buf + 0 * TILE_B, Ah, ld, k0, tid);
    stage_async(buf + 1 * TILE_B, Al, ld, k0, tid);
    stage_async(buf + 2 * TILE_B, Bh, ld, k0, tid);
    stage_async(buf + 3 * TILE_B, Bl, ld, k0, tid);
}

// ---------------------------------------------------------------------------
// Core compute for one staged k-chunk: ldmatrix fragments + 3-product bf16 mma.
// Warp tile 64x32 (2x4 warp grid).
// ---------------------------------------------------------------------------
__device__ __forceinline__ void compute_chunk(float c[4][4][4], uint32_t buf,
                                              int wm, int wn, int lane) {
    const uint32_t aH = buf, aL = buf + TILE_B;
    const uint32_t bH = buf + 2 * TILE_B, bL = buf + 3 * TILE_B;
    const int within = lane & 7, grp = lane >> 3;
    // A: groups 0/1 -> k low 8, rows +0/+8; groups 2/3 -> k high 8
    const int arow = wm * 64 + (grp & 1) * 8 + within;
    const int acol = (grp >> 1) * 8;
    // B: groups 0/1 -> n rows +0 (k low/high); groups 2/3 -> n rows +8
    const int brow = wn * 32 + (grp >> 1) * 8 + within;
    const int bcol = (grp & 1) * 8;

#pragma unroll
    for (int ks = 0; ks < 2; ks++) {
        const int kb = ks * 16;
        uint32_t bh[4][2], bl[4][2];
#pragma unroll
        for (int pi = 0; pi < 2; pi++) {
            const uint32_t o = (uint32_t)((brow + pi * 16) * PADR + kb + bcol) * 2;
            ldsm4(bh[2 * pi][0], bh[2 * pi][1], bh[2 * pi + 1][0], bh[2 * pi + 1][1], bH + o);
            ldsm4(bl[2 * pi][0], bl[2 * pi][1], bl[2 * pi + 1][0], bl[2 * pi + 1][1], bL + o);
        }
#pragma unroll
        for (int m = 0; m < 4; m++) {
            const uint32_t o = (uint32_t)((arow + m * 16) * PADR + kb + acol) * 2;
            uint32_t a0, a1, a2, a3, l0, l1, l2, l3;
            ldsm4(a0, a1, a2, a3, aH + o);
            ldsm4(l0, l1, l2, l3, aL + o);
#pragma unroll
            for (int n = 0; n < 4; n++) {
                mma_bf16(c[m][n], a0, a1, a2, a3, bh[n][0], bh[n][1]);
                mma_bf16(c[m][n], a0, a1, a2, a3, bl[n][0], bl[n][1]);
                mma_bf16(c[m][n], l0, l1, l2, l3, bh[n][0], bh[n][1]);
            }
        }
    }
}

// ---------------------------------------------------------------------------
// Kernel 1: S = (1/32) X X^T. CTA tile 128x128, grid (16, 64). NC = 32.
// ---------------------------------------------------------------------------
__global__ __launch_bounds__(256) void qk_kernel() {
    extern __shared__ char dsm[];
    const uint32_t sb = smem_u32(dsm);

    const int p = blockIdx.y;
    const int ti = blockIdx.x >> 2, tj = blockIdx.x & 3;
    const int tid = threadIdx.x;
    const int wid = tid >> 5, lane = tid & 31;
    const int wm = wid & 1, wn = wid >> 1;

    const __nv_bfloat16* Ah = g_Xh + (size_t)p * SEG * DM + (size_t)ti * 128 * DM;
    const __nv_bfloat16* Al = g_Xl + (size_t)p * SEG * DM + (size_t)ti * 128 * DM;
    const __nv_bfloat16* Bh = g_Xh + (size_t)p * SEG * DM + (size_t)tj * 128 * DM;
    const __nv_bfloat16* Bl = g_Xl + (size_t)p * SEG * DM + (size_t)tj * 128 * DM;

    float c[4][4][4];
#pragma unroll
    for (int m = 0; m < 4; m++)
#pragma unroll
        for (int n = 0; n < 4; n++)
#pragma unroll
            for (int q = 0; q < 4; q++) c[m][n][q] = 0.f;

    const int NC = DM / BK;
    stage_all(sb, Ah, Al, Bh, Bl, DM, 0, tid);
    CP_COMMIT();

    for (int kc = 0; kc < NC; kc++) {
        if (kc + 1 < NC) {
            stage_all(sb + ((kc + 1) & 1) * STAGE_B, Ah, Al, Bh, Bl, DM, (kc + 1) * BK, tid);
            CP_COMMIT();
            CP_WAIT1();
        } else {
            CP_WAIT0();
        }
        __syncthreads();
        compute_chunk(c, sb + (kc & 1) * STAGE_B, wm, wn, lane);
        __syncthreads();
    }

    const float scale = 0.03125f;  // 1/sqrt(1024)
    const int g = lane >> 2, tg = lane & 3;
    float* Sp = g_S + (size_t)p * SEG * SEG;
#pragma unroll
    for (int m = 0; m < 4; m++) {
#pragma unroll
        for (int n = 0; n < 4; n++) {
            const int row0 = ti * 128 + wm * 64 + m * 16 + g;
            const int col = tj * 128 + wn * 32 + n * 8 + 2 * tg;
            *(float2*)&Sp[(size_t)row0 * SEG + col] =
                make_float2(c[m][n][0] * scale, c[m][n][1] * scale);
            *(float2*)&Sp[(size_t)(row0 + 8) * SEG + col] =
                make_float2(c[m][n][2] * scale, c[m][n][3] * scale);
        }
    }
}

// ---------------------------------------------------------------------------
// Kernel 2: row softmax on g_S -> P hi/lo bf16. 1 block (256 thr) per row.
// ---------------------------------------------------------------------------
__global__ __launch_bounds__(256) void softmax_kernel() {
    __shared__ float smx[8];
    const size_t r = blockIdx.x;
    const float* row = g_S + r * SEG;
    const int tid = threadIdx.x;

    float v0 = row[tid], v1 = row[tid + 256];
    float m = fmaxf(v0, v1);
#pragma unroll
    for (int o = 16; o; o >>= 1) m = fmaxf(m, __shfl_xor_sync(~0u, m, o));
    if ((tid & 31) == 0) smx[tid >> 5] = m;
    __syncthreads();
    float M = smx[0];
#pragma unroll
    for (int i = 1; i < 8; i++) M = fmaxf(M, smx[i]);
    __syncthreads();

    float e0 = __expf(v0 - M), e1 = __expf(v1 - M);
    float s = e0 + e1;
#pragma unroll
    for (int o = 16; o; o >>= 1) s += __shfl_xor_sync(~0u, s, o);
    if ((tid & 31) == 0) smx[tid >> 5] = s;
    __syncthreads();
    float T = 0.f;
#pragma unroll
    for (int i = 0; i < 8; i++) T += smx[i];
    const float inv = 1.0f / T;

    const float p0 = e0 * inv, p1 = e1 * inv;
    __nv_bfloat16 h0 = __float2bfloat16_rn(p0);
    __nv_bfloat16 l0 = __float2bfloat16_rn(p0 - __bfloat162float(h0));
    __nv_bfloat16 h1 = __float2bfloat16_rn(p1);
    __nv_bfloat16 l1 = __float2bfloat16_rn(p1 - __bfloat162float(h1));
    g_Ph[r * SEG + tid] = h0;        g_Pl[r * SEG + tid] = l0;
    g_Ph[r * SEG + tid + 256] = h1;  g_Pl[r * SEG + tid + 256] = l1;
}

// ---------------------------------------------------------------------------
// Kernel 3: O = 0.25 * P @ X. CTA tile 128x128, grid (32, 64). NC = 16.
// ---------------------------------------------------------------------------
__global__ __launch_bounds__(256) void pv_kernel(float* __restrict__ out) {
    extern __shared__ char dsm[];
    const uint32_t sb = smem_u32(dsm);

    const int p = blockIdx.y;
    const int tm = blockIdx.x >> 3;
    const int tn = blockIdx.x & 7;
    const int tid = threadIdx.x;
    const int wid = tid >> 5, lane = tid & 31;
    const int wm = wid & 1, wn = wid >> 1;

    const __nv_bfloat16* Ah = g_Ph + (size_t)p * SEG * SEG + (size_t)tm * 128 * SEG;
    const __nv_bfloat16* Al = g_Pl + (size_t)p * SEG * SEG + (size_t)tm * 128 * SEG;
    const __nv_bfloat16* Bh = g_XTh + (size_t)p * DM * SEG + (size_t)tn * 128 * SEG;
    const __nv_bfloat16* Bl = g_XTl + (size_t)p * DM * SEG + (size_t)tn * 128 * SEG;

    float c[4][4][4];
#pragma unroll
    for (int m = 0; m < 4; m++)
#pragma unroll
        for (int n = 0; n < 4; n++)
#pragma unroll
            for (int q = 0; q < 4; q++) c[m][n][q] = 0.f;

    const int NC = SEG / BK;
    stage_all(sb, Ah, Al, Bh, Bl, SEG, 0, tid);
    CP_COMMIT();

    for (int kc = 0; kc < NC; kc++) {
        if (kc + 1 < NC) {
            stage_all(sb + ((kc + 1) & 1) * STAGE_B, Ah, Al, Bh, Bl, SEG, (kc + 1) * BK, tid);
            CP_COMMIT();
            CP_WAIT1();
        } else {
            CP_WAIT0();
        }
        __syncthreads();
        compute_chunk(c, sb + (kc & 1) * STAGE_B, wm, wn, lane);
        __syncthreads();
    }

    const int g = lane >> 2, tg = lane & 3;
    const int b = p >> 4, off = (p >> 2) & 3, sg = p & 3;
    const float wt = 0.25f;
#pragma unroll
    for (int m = 0; m < 4; m++) {
#pragma unroll
        for (int n = 0; n < 4; n++) {
            const int row0 = tm * 128 + wm * 64 + m * 16 + g;
            const int col = tn * 128 + wn * 32 + n * 8 + 2 * tg;
            const size_t or0 = ((size_t)b * 8192 + off + 4 * ((size_t)sg * 512 + row0)) * DM;
            const size_t or1 = ((size_t)b * 8192 + off + 4 * ((size_t)sg * 512 + row0 + 8)) * DM;
            *(float2*)(out + or0 + col) =
                make_float2(c[m][n][0] * wt, c[m][n][1] * wt);
            *(float2*)(out + or1 + col) =
                make_float2(c[m][n][2] * wt, c[m][n][3] * wt);
        }
    }
}

// ---------------------------------------------------------------------------
extern "C" void kernel_launch(void* const* d_in, const int* in_sizes, int n_in,
                              void* d_out, int out_size) {
    const float* x = (const float*)d_in[0];
    float* out = (float*)d_out;
    (void)in_sizes; (void)n_in; (void)out_size;

    cudaFuncSetAttribute(qk_kernel, cudaFuncAttributeMaxDynamicSharedMemorySize, SMEM_T);
    cudaFuncSetAttribute(pv_kernel, cudaFuncAttributeMaxDynamicSharedMemorySize, SMEM_T);

    preconvert_kernel<<<dim3(64, NPROB), 256>>>(x);
    qk_kernel<<<dim3(16, NPROB), 256, SMEM_T>>>();
    softmax_kernel<<<NPROB * SEG, 256>>>();
    pv_kernel<<<dim3(32, NPROB), 256, SMEM_T>>>(out);
}